// round 11
// baseline (speedup 1.0000x reference)
#include <cuda_runtime.h>
#include <cuda_bf16.h>
#include <cstdint>
#include <math.h>

#define NSEQ 4096
#define DM   512
#define NH   8
#define DH   64
#define TSTRIDE 72   // smem row stride in elements (144B): 16B-aligned, ldmatrix conflict-free

// ---------------- static scratch ----------------
__device__ __nv_bfloat16 g_Qb[NSEQ * DM];
__device__ __nv_bfloat16 g_Kb[NSEQ * DM];
__device__ __nv_bfloat16 g_Vb[NSEQ * DM];
__device__ __nv_bfloat16 g_Wq[DM * DM];
__device__ __nv_bfloat16 g_Wk[DM * DM];
__device__ __nv_bfloat16 g_Wv[DM * DM];
__device__ __nv_bfloat16 g_Wo[DM * DM];
__device__ __nv_bfloat16 g_Qp[NSEQ * DM];   // projected Q, pre-scaled by log2(e)/8
__device__ __nv_bfloat16 g_Kp[NSEQ * DM];
__device__ __nv_bfloat16 g_Vp[NSEQ * DM];
__device__ __nv_bfloat16 g_ctxb[NSEQ * DM];
__device__ float         g_tmp[NSEQ * DM];

// ---------------- helpers ----------------
__device__ __forceinline__ uint32_t smem_u32(const void* p) {
    uint32_t a;
    asm("{ .reg .u64 t; cvta.to.shared.u64 t, %1; cvt.u32.u64 %0, t; }" : "=r"(a) : "l"(p));
    return a;
}

// single-instruction MUFU.EX2 regardless of compiler math flags
__device__ __forceinline__ float ex2_fast(float x) {
    float y;
    asm("ex2.approx.ftz.f32 %0, %1;" : "=f"(y) : "f"(x));
    return y;
}

#define LDSM4(R, addr) \
    asm volatile("ldmatrix.sync.aligned.m8n8.x4.shared.b16 {%0,%1,%2,%3}, [%4];" \
        : "=r"((R)[0]), "=r"((R)[1]), "=r"((R)[2]), "=r"((R)[3]) : "r"(addr))

#define LDSM4T(R, addr) \
    asm volatile("ldmatrix.sync.aligned.m8n8.x4.trans.shared.b16 {%0,%1,%2,%3}, [%4];" \
        : "=r"((R)[0]), "=r"((R)[1]), "=r"((R)[2]), "=r"((R)[3]) : "r"(addr))

#define MMA16816(C, A, B0, B1) \
    asm volatile("mma.sync.aligned.m16n8k16.row.col.f32.bf16.bf16.f32 " \
        "{%0,%1,%2,%3},{%4,%5,%6,%7},{%8,%9},{%0,%1,%2,%3};" \
        : "+f"((C)[0]), "+f"((C)[1]), "+f"((C)[2]), "+f"((C)[3]) \
        : "r"((A)[0]), "r"((A)[1]), "r"((A)[2]), "r"((A)[3]), "r"(B0), "r"(B1))

#define CPA16(dst, src) \
    asm volatile("cp.async.cg.shared.global [%0], [%1], 16;" :: "r"(dst), "l"(src))
#define CPC() asm volatile("cp.async.commit_group;" ::: "memory")
#define CPW(n) asm volatile("cp.async.wait_group %0;" :: "n"(n) : "memory")

__device__ __forceinline__ uint32_t packbf(float a, float b) {
    __nv_bfloat162 t = __floats2bfloat162_rn(a, b);
    return *reinterpret_cast<uint32_t*>(&t);
}

// ---------------- fp32 -> bf16 convert ----------------
__global__ void __launch_bounds__(256) cvt_kernel(const float* __restrict__ in,
                                                  __nv_bfloat16* __restrict__ out, int n4) {
    int i = blockIdx.x * 256 + threadIdx.x;
    if (i >= n4) return;
    float4 v = ((const float4*)in)[i];
    ((__nv_bfloat162*)out)[2 * i]     = __floats2bfloat162_rn(v.x, v.y);
    ((__nv_bfloat162*)out)[2 * i + 1] = __floats2bfloat162_rn(v.z, v.w);
}

// ============================================================================
// GEMM: C[4096,512] = A[4096,512] @ W[512,512]^T, bf16 mma.sync.
// Epilogue: v = (acc + bias[n]) * scale;  RESID=1 adds fp32 R and stores fp32,
// RESID=0 stores bf16. Block 128x128, K-chunk 64, 8 warps (4Mx2N, 32x64 each).
// ============================================================================
template<int RESID>
__global__ void __launch_bounds__(256) gemm_mma(
    const __nv_bfloat16* __restrict__ A, const __nv_bfloat16* __restrict__ W,
    const float* __restrict__ bias, const float* __restrict__ R,
    void* __restrict__ Cout, float scale)
{
    extern __shared__ __align__(16) __nv_bfloat16 sm[];
    __nv_bfloat16* sA = sm;                       // [2][128][TSTRIDE]
    __nv_bfloat16* sB = sm + 2 * 128 * TSTRIDE;   // [2][128][TSTRIDE]
    const int tid = threadIdx.x, lane = tid & 31, wid = tid >> 5;
    const int mb = blockIdx.y * 128, nb = blockIdx.x * 128;
    const int wm = wid & 3, wn = wid >> 2;

    const int lrow = tid >> 1, lcol = (tid & 1) * 32;
    const __nv_bfloat16* gA = A + (size_t)(mb + lrow) * DM + lcol;
    const __nv_bfloat16* gB = W + (size_t)(nb + lrow) * DM + lcol;
    const uint32_t sAb = smem_u32(sA) + (lrow * TSTRIDE + lcol) * 2;
    const uint32_t sBb = smem_u32(sB) + (lrow * TSTRIDE + lcol) * 2;
    const uint32_t BUF = 128 * TSTRIDE * 2;

    float acc[2][8][4];
#pragma unroll
    for (int a = 0; a < 2; a++)
#pragma unroll
        for (int b = 0; b < 8; b++)
#pragma unroll
            for (int c = 0; c < 4; c++) acc[a][b][c] = 0.f;

#pragma unroll
    for (int j = 0; j < 4; j++) { CPA16(sAb + j * 16, gA + j * 8); CPA16(sBb + j * 16, gB + j * 8); }
    CPC();

    for (int it = 0; it < 8; ++it) {
        if (it < 7) {
            const __nv_bfloat16* a1 = gA + (it + 1) * 64;
            const __nv_bfloat16* b1 = gB + (it + 1) * 64;
            uint32_t da = sAb + ((it + 1) & 1) * BUF, db = sBb + ((it + 1) & 1) * BUF;
#pragma unroll
            for (int j = 0; j < 4; j++) { CPA16(da + j * 16, a1 + j * 8); CPA16(db + j * 16, b1 + j * 8); }
            CPC();
            CPW(1);
        } else {
            CPW(0);
        }
        __syncthreads();

        const uint32_t bA = smem_u32(sA) + (it & 1) * BUF;
        const uint32_t bB = smem_u32(sB) + (it & 1) * BUF;
#pragma unroll
        for (int ks = 0; ks < 4; ++ks) {
            uint32_t afr[2][4];
#pragma unroll
            for (int mt = 0; mt < 2; ++mt) {
                uint32_t ad = bA + ((wm * 32 + mt * 16 + ((lane >> 3) & 1) * 8 + (lane & 7)) * TSTRIDE
                                   + ks * 16 + (lane >> 4) * 8) * 2;
                LDSM4(afr[mt], ad);
            }
#pragma unroll
            for (int p = 0; p < 4; ++p) {
                uint32_t bfr[4];
                uint32_t bd = bB + ((wn * 64 + p * 16 + (lane >> 4) * 8 + (lane & 7)) * TSTRIDE
                                   + ks * 16 + ((lane >> 3) & 1) * 8) * 2;
                LDSM4(bfr, bd);
#pragma unroll
                for (int mt = 0; mt < 2; ++mt) {
                    MMA16816(acc[mt][2 * p],     afr[mt], bfr[0], bfr[1]);
                    MMA16816(acc[mt][2 * p + 1], afr[mt], bfr[2], bfr[3]);
                }
            }
        }
        __syncthreads();
    }

    const int r = lane >> 2, cc = (lane & 3) * 2;
#pragma unroll
    for (int mt = 0; mt < 2; ++mt) {
#pragma unroll
        for (int nt = 0; nt < 8; ++nt) {
            int m0 = mb + wm * 32 + mt * 16 + r;
            int n  = nb + wn * 64 + nt * 8 + cc;
            float b0 = bias[n], b1 = bias[n + 1];
            float v00 = (acc[mt][nt][0] + b0) * scale;
            float v01 = (acc[mt][nt][1] + b1) * scale;
            float v10 = (acc[mt][nt][2] + b0) * scale;
            float v11 = (acc[mt][nt][3] + b1) * scale;
            if (RESID) {
                const float* r0 = R + (size_t)m0 * DM + n;
                const float* r1 = R + (size_t)(m0 + 8) * DM + n;
                float2 o0 = make_float2(v00 + r0[0], v01 + r0[1]);
                float2 o1 = make_float2(v10 + r1[0], v11 + r1[1]);
                *(float2*)((float*)Cout + (size_t)m0 * DM + n)       = o0;
                *(float2*)((float*)Cout + (size_t)(m0 + 8) * DM + n) = o1;
            } else {
                *(__nv_bfloat162*)((__nv_bfloat16*)Cout + (size_t)m0 * DM + n)       = __floats2bfloat162_rn(v00, v01);
                *(__nv_bfloat162*)((__nv_bfloat16*)Cout + (size_t)(m0 + 8) * DM + n) = __floats2bfloat162_rn(v10, v11);
            }
        }
    }
}

// ============================================================================
// Flash attention, mma.sync. Block = 256 thr = 128 queries x 1 head.
// Warp w owns q-rows w*16..w*16+15 and all 128 keys of each tile: softmax is
// warp-local; S accumulators convert in-register to P a-frags. No-max softmax
// (ex2.approx; log2e/8 folded into Q projection). V via ldmatrix.trans.
// (Structure identical to R4's measured-fast kernel; only exp2f -> ex2_fast.)
// ============================================================================
__global__ void __launch_bounds__(256) flash_mma(
    const __nv_bfloat16* __restrict__ Qp, const __nv_bfloat16* __restrict__ Kp,
    const __nv_bfloat16* __restrict__ Vp, __nv_bfloat16* __restrict__ ctx)
{
    extern __shared__ __align__(16) __nv_bfloat16 sm[];
    __nv_bfloat16* sQ = sm;                       // [128][TSTRIDE]
    __nv_bfloat16* sK = sm + 128 * TSTRIDE;       // [2][128][TSTRIDE]
    __nv_bfloat16* sV = sK + 2 * 128 * TSTRIDE;   // [2][128][TSTRIDE]
    const int tid = threadIdx.x, lane = tid & 31, wid = tid >> 5;
    const int h = blockIdx.y, q0 = blockIdx.x * 128;

    const int lrow = tid >> 1, lcol = (tid & 1) * 32;
    {
        const uint4* g = (const uint4*)(Qp + (size_t)(q0 + lrow) * DM + h * DH + lcol);
        uint4* s = (uint4*)(sQ + lrow * TSTRIDE + lcol);
#pragma unroll
        for (int j = 0; j < 4; j++) s[j] = g[j];
    }
    const __nv_bfloat16* gK = Kp + (size_t)lrow * DM + h * DH + lcol;
    const __nv_bfloat16* gV = Vp + (size_t)lrow * DM + h * DH + lcol;
    const uint32_t sKb = smem_u32(sK) + (lrow * TSTRIDE + lcol) * 2;
    const uint32_t sVb = smem_u32(sV) + (lrow * TSTRIDE + lcol) * 2;
    const uint32_t BUF = 128 * TSTRIDE * 2;
    const size_t TILE = (size_t)128 * DM;

#pragma unroll
    for (int j = 0; j < 4; j++) { CPA16(sKb + j * 16, gK + j * 8); CPA16(sVb + j * 16, gV + j * 8); }
    CPC();
    __syncthreads();

    uint32_t qf[4][4];
#pragma unroll
    for (int ks = 0; ks < 4; ks++) {
        uint32_t ad = smem_u32(sQ) + ((wid * 16 + ((lane >> 3) & 1) * 8 + (lane & 7)) * TSTRIDE
                                      + ks * 16 + (lane >> 4) * 8) * 2;
        LDSM4(qf[ks], ad);
    }

    float o[8][4];
#pragma unroll
    for (int a = 0; a < 8; a++)
#pragma unroll
        for (int b = 0; b < 4; b++) o[a][b] = 0.f;
    float rs0 = 0.f, rs1 = 0.f;

    for (int kt = 0; kt < 32; ++kt) {
        if (kt < 31) {
            const __nv_bfloat16* k1 = gK + (kt + 1) * TILE;
            const __nv_bfloat16* v1 = gV + (kt + 1) * TILE;
            uint32_t dk = sKb + ((kt + 1) & 1) * BUF, dv = sVb + ((kt + 1) & 1) * BUF;
#pragma unroll
            for (int j = 0; j < 4; j++) { CPA16(dk + j * 16, k1 + j * 8); CPA16(dv + j * 16, v1 + j * 8); }
            CPC();
            CPW(1);
        } else {
            CPW(0);
        }
        __syncthreads();

        const uint32_t bK = smem_u32(sK) + (kt & 1) * BUF;
        const uint32_t bV = smem_u32(sV) + (kt & 1) * BUF;

        // S = Q @ K^T : per-warp 16 x 128
        float s[16][4];
#pragma unroll
        for (int a = 0; a < 16; a++)
#pragma unroll
            for (int b = 0; b < 4; b++) s[a][b] = 0.f;
#pragma unroll
        for (int ks = 0; ks < 4; ++ks) {
#pragma unroll
            for (int p = 0; p < 8; ++p) {
                uint32_t bfr[4];
                uint32_t bd = bK + ((p * 16 + (lane >> 4) * 8 + (lane & 7)) * TSTRIDE
                                   + ks * 16 + ((lane >> 3) & 1) * 8) * 2;
                LDSM4(bfr, bd);
                MMA16816(s[2 * p],     qf[ks], bfr[0], bfr[1]);
                MMA16816(s[2 * p + 1], qf[ks], bfr[2], bfr[3]);
            }
        }

        // exp2 (MUFU) + row-sum + pack into P a-frags
        uint32_t pa[8][4];
#pragma unroll
        for (int j = 0; j < 8; ++j) {
            float e00 = ex2_fast(s[2 * j][0]),     e01 = ex2_fast(s[2 * j][1]);
            float e10 = ex2_fast(s[2 * j][2]),     e11 = ex2_fast(s[2 * j][3]);
            float f00 = ex2_fast(s[2 * j + 1][0]), f01 = ex2_fast(s[2 * j + 1][1]);
            float f10 = ex2_fast(s[2 * j + 1][2]), f11 = ex2_fast(s[2 * j + 1][3]);
            rs0 += e00 + e01 + f00 + f01;
            rs1 += e10 + e11 + f10 + f11;
            pa[j][0] = packbf(e00, e01);
            pa[j][1] = packbf(e10, e11);
            pa[j][2] = packbf(f00, f01);
            pa[j][3] = packbf(f10, f11);
        }

        // O += P @ V
#pragma unroll
        for (int j = 0; j < 8; ++j) {
#pragma unroll
            for (int p = 0; p < 4; ++p) {
                uint32_t vfr[4];
                uint32_t vd = bV + ((j * 16 + ((lane >> 3) & 1) * 8 + (lane & 7)) * TSTRIDE
                                   + p * 16 + (lane >> 4) * 8) * 2;
                LDSM4T(vfr, vd);
                MMA16816(o[2 * p],     pa[j], vfr[0], vfr[1]);
                MMA16816(o[2 * p + 1], pa[j], vfr[2], vfr[3]);
            }
        }
        __syncthreads();
    }

    rs0 += __shfl_xor_sync(0xffffffffu, rs0, 1);
    rs0 += __shfl_xor_sync(0xffffffffu, rs0, 2);
    rs1 += __shfl_xor_sync(0xffffffffu, rs1, 1);
    rs1 += __shfl_xor_sync(0xffffffffu, rs1, 2);
    float i0 = 1.f / rs0, i1 = 1.f / rs1;

    const int r = lane >> 2, cc = (lane & 3) * 2;
    const int m0 = q0 + wid * 16 + r;
#pragma unroll
    for (int nt = 0; nt < 8; ++nt) {
        int col = h * DH + nt * 8 + cc;
        *(__nv_bfloat162*)(ctx + (size_t)m0 * DM + col)       = __floats2bfloat162_rn(o[nt][0] * i0, o[nt][1] * i0);
        *(__nv_bfloat162*)(ctx + (size_t)(m0 + 8) * DM + col) = __floats2bfloat162_rn(o[nt][2] * i1, o[nt][3] * i1);
    }
}

// ============================================================================
// LayerNorm: one block (128 thr) per row; float4 + warp shuffles.
// ============================================================================
__global__ void __launch_bounds__(128) ln_kernel(
    const float* __restrict__ X, const float* __restrict__ gamma,
    const float* __restrict__ beta, float* __restrict__ out)
{
    __shared__ float ws[4], ws2[4];
    const int row = blockIdx.x, t = threadIdx.x, lane = t & 31, w = t >> 5;
    float4 x = ((const float4*)(X + (size_t)row * DM))[t];

    float s = x.x + x.y + x.z + x.w;
#pragma unroll
    for (int o = 16; o > 0; o >>= 1) s += __shfl_xor_sync(0xffffffffu, s, o);
    if (lane == 0) ws[w] = s;
    __syncthreads();
    float mean = (ws[0] + ws[1] + ws[2] + ws[3]) * (1.f / DM);

    float d0 = x.x - mean, d1 = x.y - mean, d2 = x.z - mean, d3 = x.w - mean;
    float v = d0 * d0 + d1 * d1 + d2 * d2 + d3 * d3;
#pragma unroll
    for (int o = 16; o > 0; o >>= 1) v += __shfl_xor_sync(0xffffffffu, v, o);
    if (lane == 0) ws2[w] = v;
    __syncthreads();
    float rstd = rsqrtf((ws2[0] + ws2[1] + ws2[2] + ws2[3]) * (1.f / DM) + 1e-5f);

    float4 g = ((const float4*)gamma)[t];
    float4 b = ((const float4*)beta)[t];
    float4 o4 = make_float4(d0 * rstd * g.x + b.x, d1 * rstd * g.y + b.y,
                            d2 * rstd * g.z + b.z, d3 * rstd * g.w + b.w);
    ((float4*)(out + (size_t)row * DM))[t] = o4;
}

// ============================================================================
extern "C" void kernel_launch(void* const* d_in, const int* in_sizes, int n_in,
                              void* d_out, int out_size)
{
    const float* Q    = (const float*)d_in[0];
    const float* K    = (const float*)d_in[1];
    const float* V    = (const float*)d_in[2];
    const float* WQ   = (const float*)d_in[3];
    const float* bQ   = (const float*)d_in[4];
    const float* WK   = (const float*)d_in[5];
    const float* bK   = (const float*)d_in[6];
    const float* WV   = (const float*)d_in[7];
    const float* bV   = (const float*)d_in[8];
    const float* WO   = (const float*)d_in[9];
    const float* bO   = (const float*)d_in[10];
    const float* gamma= (const float*)d_in[11];
    const float* beta = (const float*)d_in[12];
    float* out = (float*)d_out;

    __nv_bfloat16 *Qb, *Kb, *Vb, *Wq, *Wk, *Wv, *Wo, *Qp, *Kp, *Vp, *ctxb;
    float* tmp;
    cudaGetSymbolAddress((void**)&Qb, g_Qb);
    cudaGetSymbolAddress((void**)&Kb, g_Kb);
    cudaGetSymbolAddress((void**)&Vb, g_Vb);
    cudaGetSymbolAddress((void**)&Wq, g_Wq);
    cudaGetSymbolAddress((void**)&Wk, g_Wk);
    cudaGetSymbolAddress((void**)&Wv, g_Wv);
    cudaGetSymbolAddress((void**)&Wo, g_Wo);
    cudaGetSymbolAddress((void**)&Qp, g_Qp);
    cudaGetSymbolAddress((void**)&Kp, g_Kp);
    cudaGetSymbolAddress((void**)&Vp, g_Vp);
    cudaGetSymbolAddress((void**)&ctxb, g_ctxb);
    cudaGetSymbolAddress((void**)&tmp, g_tmp);

    const int GEMM_SMEM  = 4 * 128 * TSTRIDE * 2;   // 73728
    const int FLASH_SMEM = 5 * 128 * TSTRIDE * 2;   // 92160
    cudaFuncSetAttribute(gemm_mma<0>, cudaFuncAttributeMaxDynamicSharedMemorySize, GEMM_SMEM);
    cudaFuncSetAttribute(gemm_mma<1>, cudaFuncAttributeMaxDynamicSharedMemorySize, GEMM_SMEM);
    cudaFuncSetAttribute(flash_mma,   cudaFuncAttributeMaxDynamicSharedMemorySize, FLASH_SMEM);

    const int n_in4 = NSEQ * DM / 4, n_w4 = DM * DM / 4;
    cvt_kernel<<<n_in4 / 256, 256>>>(Q, Qb, n_in4);
    cvt_kernel<<<n_in4 / 256, 256>>>(K, Kb, n_in4);
    cvt_kernel<<<n_in4 / 256, 256>>>(V, Vb, n_in4);
    cvt_kernel<<<n_w4 / 256, 256>>>(WQ, Wq, n_w4);
    cvt_kernel<<<n_w4 / 256, 256>>>(WK, Wk, n_w4);
    cvt_kernel<<<n_w4 / 256, 256>>>(WV, Wv, n_w4);
    cvt_kernel<<<n_w4 / 256, 256>>>(WO, Wo, n_w4);

    dim3 gg(DM / 128, NSEQ / 128);   // (4, 32)
    const float QSCALE = 0.125f * 1.44269504088896340736f;  // fold log2e into Q
    gemm_mma<0><<<gg, 256, GEMM_SMEM>>>(Qb, Wq, bQ, nullptr, Qp, QSCALE);
    gemm_mma<0><<<gg, 256, GEMM_SMEM>>>(Kb, Wk, bK, nullptr, Kp, 1.0f);
    gemm_mma<0><<<gg, 256, GEMM_SMEM>>>(Vb, Wv, bV, nullptr, Vp, 1.0f);

    flash_mma<<<dim3(NSEQ / 128, NH), 256, FLASH_SMEM>>>(Qp, Kp, Vp, ctxb);

    gemm_mma<1><<<gg, 256, GEMM_SMEM>>>(ctxb, Wo, bO, Q, tmp, 1.0f);

    ln_kernel<<<NSEQ, 128>>>(tmp, gamma, beta, out);
}

// round 12
// speedup vs baseline: 1.0026x; 1.0026x over previous
#include <cuda_runtime.h>
#include <cuda_bf16.h>
#include <cstdint>
#include <math.h>

#define NSEQ 4096
#define DM   512
#define NH   8
#define DH   64
#define TSTRIDE 72   // smem row stride in elements (144B): 16B-aligned, ldmatrix conflict-free

// ---------------- static scratch ----------------
__device__ __nv_bfloat16 g_Qb[NSEQ * DM];
__device__ __nv_bfloat16 g_Kb[NSEQ * DM];
__device__ __nv_bfloat16 g_Vb[NSEQ * DM];
__device__ __nv_bfloat16 g_Wq[DM * DM];
__device__ __nv_bfloat16 g_Wk[DM * DM];
__device__ __nv_bfloat16 g_Wv[DM * DM];
__device__ __nv_bfloat16 g_Wo[DM * DM];
__device__ __nv_bfloat16 g_Qp[NSEQ * DM];   // projected Q, pre-scaled by log2(e)/8
__device__ __nv_bfloat16 g_Kp[NSEQ * DM];
__device__ __nv_bfloat16 g_Vp[NSEQ * DM];
__device__ __nv_bfloat16 g_ctxb[NSEQ * DM];
__device__ float         g_tmp[NSEQ * DM];

// ---------------- helpers ----------------
__device__ __forceinline__ uint32_t smem_u32(const void* p) {
    uint32_t a;
    asm("{ .reg .u64 t; cvta.to.shared.u64 t, %1; cvt.u32.u64 %0, t; }" : "=r"(a) : "l"(p));
    return a;
}

// single-instruction MUFU.EX2 regardless of compiler math flags
__device__ __forceinline__ float ex2_fast(float x) {
    float y;
    asm("ex2.approx.ftz.f32 %0, %1;" : "=f"(y) : "f"(x));
    return y;
}

#define LDSM4(R, addr) \
    asm volatile("ldmatrix.sync.aligned.m8n8.x4.shared.b16 {%0,%1,%2,%3}, [%4];" \
        : "=r"((R)[0]), "=r"((R)[1]), "=r"((R)[2]), "=r"((R)[3]) : "r"(addr))

#define LDSM4T(R, addr) \
    asm volatile("ldmatrix.sync.aligned.m8n8.x4.trans.shared.b16 {%0,%1,%2,%3}, [%4];" \
        : "=r"((R)[0]), "=r"((R)[1]), "=r"((R)[2]), "=r"((R)[3]) : "r"(addr))

#define MMA16816(C, A, B0, B1) \
    asm volatile("mma.sync.aligned.m16n8k16.row.col.f32.bf16.bf16.f32 " \
        "{%0,%1,%2,%3},{%4,%5,%6,%7},{%8,%9},{%0,%1,%2,%3};" \
        : "+f"((C)[0]), "+f"((C)[1]), "+f"((C)[2]), "+f"((C)[3]) \
        : "r"((A)[0]), "r"((A)[1]), "r"((A)[2]), "r"((A)[3]), "r"(B0), "r"(B1))

#define CPA16(dst, src) \
    asm volatile("cp.async.cg.shared.global [%0], [%1], 16;" :: "r"(dst), "l"(src))
#define CPC() asm volatile("cp.async.commit_group;" ::: "memory")
#define CPW(n) asm volatile("cp.async.wait_group %0;" :: "n"(n) : "memory")

__device__ __forceinline__ uint32_t packbf(float a, float b) {
    __nv_bfloat162 t = __floats2bfloat162_rn(a, b);
    return *reinterpret_cast<uint32_t*>(&t);
}

// ---------------- fp32 -> bf16 convert ----------------
__global__ void __launch_bounds__(256) cvt_kernel(const float* __restrict__ in,
                                                  __nv_bfloat16* __restrict__ out, int n4) {
    int i = blockIdx.x * 256 + threadIdx.x;
    if (i >= n4) return;
    float4 v = ((const float4*)in)[i];
    ((__nv_bfloat162*)out)[2 * i]     = __floats2bfloat162_rn(v.x, v.y);
    ((__nv_bfloat162*)out)[2 * i + 1] = __floats2bfloat162_rn(v.z, v.w);
}

// ============================================================================
// GEMM: C[4096,512] = A[4096,512] @ W[512,512]^T, bf16 mma.sync.
// Epilogue: v = (acc + bias[n]) * scale;  RESID=1 adds fp32 R and stores fp32,
// RESID=0 stores bf16. Block 128x128, K-chunk 64, 8 warps (4Mx2N, 32x64 each).
// ============================================================================
template<int RESID>
__global__ void __launch_bounds__(256) gemm_mma(
    const __nv_bfloat16* __restrict__ A, const __nv_bfloat16* __restrict__ W,
    const float* __restrict__ bias, const float* __restrict__ R,
    void* __restrict__ Cout, float scale)
{
    extern __shared__ __align__(16) __nv_bfloat16 sm[];
    __nv_bfloat16* sA = sm;                       // [2][128][TSTRIDE]
    __nv_bfloat16* sB = sm + 2 * 128 * TSTRIDE;   // [2][128][TSTRIDE]
    const int tid = threadIdx.x, lane = tid & 31, wid = tid >> 5;
    const int mb = blockIdx.y * 128, nb = blockIdx.x * 128;
    const int wm = wid & 3, wn = wid >> 2;

    const int lrow = tid >> 1, lcol = (tid & 1) * 32;
    const __nv_bfloat16* gA = A + (size_t)(mb + lrow) * DM + lcol;
    const __nv_bfloat16* gB = W + (size_t)(nb + lrow) * DM + lcol;
    const uint32_t sAb = smem_u32(sA) + (lrow * TSTRIDE + lcol) * 2;
    const uint32_t sBb = smem_u32(sB) + (lrow * TSTRIDE + lcol) * 2;
    const uint32_t BUF = 128 * TSTRIDE * 2;

    float acc[2][8][4];
#pragma unroll
    for (int a = 0; a < 2; a++)
#pragma unroll
        for (int b = 0; b < 8; b++)
#pragma unroll
            for (int c = 0; c < 4; c++) acc[a][b][c] = 0.f;

#pragma unroll
    for (int j = 0; j < 4; j++) { CPA16(sAb + j * 16, gA + j * 8); CPA16(sBb + j * 16, gB + j * 8); }
    CPC();

    for (int it = 0; it < 8; ++it) {
        if (it < 7) {
            const __nv_bfloat16* a1 = gA + (it + 1) * 64;
            const __nv_bfloat16* b1 = gB + (it + 1) * 64;
            uint32_t da = sAb + ((it + 1) & 1) * BUF, db = sBb + ((it + 1) & 1) * BUF;
#pragma unroll
            for (int j = 0; j < 4; j++) { CPA16(da + j * 16, a1 + j * 8); CPA16(db + j * 16, b1 + j * 8); }
            CPC();
            CPW(1);
        } else {
            CPW(0);
        }
        __syncthreads();

        const uint32_t bA = smem_u32(sA) + (it & 1) * BUF;
        const uint32_t bB = smem_u32(sB) + (it & 1) * BUF;
#pragma unroll
        for (int ks = 0; ks < 4; ++ks) {
            uint32_t afr[2][4];
#pragma unroll
            for (int mt = 0; mt < 2; ++mt) {
                uint32_t ad = bA + ((wm * 32 + mt * 16 + ((lane >> 3) & 1) * 8 + (lane & 7)) * TSTRIDE
                                   + ks * 16 + (lane >> 4) * 8) * 2;
                LDSM4(afr[mt], ad);
            }
#pragma unroll
            for (int p = 0; p < 4; ++p) {
                uint32_t bfr[4];
                uint32_t bd = bB + ((wn * 64 + p * 16 + (lane >> 4) * 8 + (lane & 7)) * TSTRIDE
                                   + ks * 16 + ((lane >> 3) & 1) * 8) * 2;
                LDSM4(bfr, bd);
#pragma unroll
                for (int mt = 0; mt < 2; ++mt) {
                    MMA16816(acc[mt][2 * p],     afr[mt], bfr[0], bfr[1]);
                    MMA16816(acc[mt][2 * p + 1], afr[mt], bfr[2], bfr[3]);
                }
            }
        }
        __syncthreads();
    }

    const int r = lane >> 2, cc = (lane & 3) * 2;
#pragma unroll
    for (int mt = 0; mt < 2; ++mt) {
#pragma unroll
        for (int nt = 0; nt < 8; ++nt) {
            int m0 = mb + wm * 32 + mt * 16 + r;
            int n  = nb + wn * 64 + nt * 8 + cc;
            float b0 = bias[n], b1 = bias[n + 1];
            float v00 = (acc[mt][nt][0] + b0) * scale;
            float v01 = (acc[mt][nt][1] + b1) * scale;
            float v10 = (acc[mt][nt][2] + b0) * scale;
            float v11 = (acc[mt][nt][3] + b1) * scale;
            if (RESID) {
                const float* r0 = R + (size_t)m0 * DM + n;
                const float* r1 = R + (size_t)(m0 + 8) * DM + n;
                float2 o0 = make_float2(v00 + r0[0], v01 + r0[1]);
                float2 o1 = make_float2(v10 + r1[0], v11 + r1[1]);
                *(float2*)((float*)Cout + (size_t)m0 * DM + n)       = o0;
                *(float2*)((float*)Cout + (size_t)(m0 + 8) * DM + n) = o1;
            } else {
                *(__nv_bfloat162*)((__nv_bfloat16*)Cout + (size_t)m0 * DM + n)       = __floats2bfloat162_rn(v00, v01);
                *(__nv_bfloat162*)((__nv_bfloat16*)Cout + (size_t)(m0 + 8) * DM + n) = __floats2bfloat162_rn(v10, v11);
            }
        }
    }
}

// ============================================================================
// Flash attention, mma.sync. Block = 256 thr = 128 queries x 1 head.
// Warp w owns q-rows w*16..w*16+15 and all 128 keys of each tile: softmax is
// warp-local; S accumulators convert in-register to P a-frags. No-max softmax
// (ex2.approx; log2e/8 folded into Q projection). V via ldmatrix.trans.
// (Structure identical to R4's measured-fast kernel; only exp2f -> ex2_fast.)
// ============================================================================
__global__ void __launch_bounds__(256) flash_mma(
    const __nv_bfloat16* __restrict__ Qp, const __nv_bfloat16* __restrict__ Kp,
    const __nv_bfloat16* __restrict__ Vp, __nv_bfloat16* __restrict__ ctx)
{
    extern __shared__ __align__(16) __nv_bfloat16 sm[];
    __nv_bfloat16* sQ = sm;                       // [128][TSTRIDE]
    __nv_bfloat16* sK = sm + 128 * TSTRIDE;       // [2][128][TSTRIDE]
    __nv_bfloat16* sV = sK + 2 * 128 * TSTRIDE;   // [2][128][TSTRIDE]
    const int tid = threadIdx.x, lane = tid & 31, wid = tid >> 5;
    const int h = blockIdx.y, q0 = blockIdx.x * 128;

    const int lrow = tid >> 1, lcol = (tid & 1) * 32;
    {
        const uint4* g = (const uint4*)(Qp + (size_t)(q0 + lrow) * DM + h * DH + lcol);
        uint4* s = (uint4*)(sQ + lrow * TSTRIDE + lcol);
#pragma unroll
        for (int j = 0; j < 4; j++) s[j] = g[j];
    }
    const __nv_bfloat16* gK = Kp + (size_t)lrow * DM + h * DH + lcol;
    const __nv_bfloat16* gV = Vp + (size_t)lrow * DM + h * DH + lcol;
    const uint32_t sKb = smem_u32(sK) + (lrow * TSTRIDE + lcol) * 2;
    const uint32_t sVb = smem_u32(sV) + (lrow * TSTRIDE + lcol) * 2;
    const uint32_t BUF = 128 * TSTRIDE * 2;
    const size_t TILE = (size_t)128 * DM;

#pragma unroll
    for (int j = 0; j < 4; j++) { CPA16(sKb + j * 16, gK + j * 8); CPA16(sVb + j * 16, gV + j * 8); }
    CPC();
    __syncthreads();

    uint32_t qf[4][4];
#pragma unroll
    for (int ks = 0; ks < 4; ks++) {
        uint32_t ad = smem_u32(sQ) + ((wid * 16 + ((lane >> 3) & 1) * 8 + (lane & 7)) * TSTRIDE
                                      + ks * 16 + (lane >> 4) * 8) * 2;
        LDSM4(qf[ks], ad);
    }

    float o[8][4];
#pragma unroll
    for (int a = 0; a < 8; a++)
#pragma unroll
        for (int b = 0; b < 4; b++) o[a][b] = 0.f;
    float rs0 = 0.f, rs1 = 0.f;

    for (int kt = 0; kt < 32; ++kt) {
        if (kt < 31) {
            const __nv_bfloat16* k1 = gK + (kt + 1) * TILE;
            const __nv_bfloat16* v1 = gV + (kt + 1) * TILE;
            uint32_t dk = sKb + ((kt + 1) & 1) * BUF, dv = sVb + ((kt + 1) & 1) * BUF;
#pragma unroll
            for (int j = 0; j < 4; j++) { CPA16(dk + j * 16, k1 + j * 8); CPA16(dv + j * 16, v1 + j * 8); }
            CPC();
            CPW(1);
        } else {
            CPW(0);
        }
        __syncthreads();

        const uint32_t bK = smem_u32(sK) + (kt & 1) * BUF;
        const uint32_t bV = smem_u32(sV) + (kt & 1) * BUF;

        // S = Q @ K^T : per-warp 16 x 128
        float s[16][4];
#pragma unroll
        for (int a = 0; a < 16; a++)
#pragma unroll
            for (int b = 0; b < 4; b++) s[a][b] = 0.f;
#pragma unroll
        for (int ks = 0; ks < 4; ++ks) {
#pragma unroll
            for (int p = 0; p < 8; ++p) {
                uint32_t bfr[4];
                uint32_t bd = bK + ((p * 16 + (lane >> 4) * 8 + (lane & 7)) * TSTRIDE
                                   + ks * 16 + ((lane >> 3) & 1) * 8) * 2;
                LDSM4(bfr, bd);
                MMA16816(s[2 * p],     qf[ks], bfr[0], bfr[1]);
                MMA16816(s[2 * p + 1], qf[ks], bfr[2], bfr[3]);
            }
        }

        // exp2 (MUFU) + row-sum + pack into P a-frags
        uint32_t pa[8][4];
#pragma unroll
        for (int j = 0; j < 8; ++j) {
            float e00 = ex2_fast(s[2 * j][0]),     e01 = ex2_fast(s[2 * j][1]);
            float e10 = ex2_fast(s[2 * j][2]),     e11 = ex2_fast(s[2 * j][3]);
            float f00 = ex2_fast(s[2 * j + 1][0]), f01 = ex2_fast(s[2 * j + 1][1]);
            float f10 = ex2_fast(s[2 * j + 1][2]), f11 = ex2_fast(s[2 * j + 1][3]);
            rs0 += e00 + e01 + f00 + f01;
            rs1 += e10 + e11 + f10 + f11;
            pa[j][0] = packbf(e00, e01);
            pa[j][1] = packbf(e10, e11);
            pa[j][2] = packbf(f00, f01);
            pa[j][3] = packbf(f10, f11);
        }

        // O += P @ V
#pragma unroll
        for (int j = 0; j < 8; ++j) {
#pragma unroll
            for (int p = 0; p < 4; ++p) {
                uint32_t vfr[4];
                uint32_t vd = bV + ((j * 16 + ((lane >> 3) & 1) * 8 + (lane & 7)) * TSTRIDE
                                   + p * 16 + (lane >> 4) * 8) * 2;
                LDSM4T(vfr, vd);
                MMA16816(o[2 * p],     pa[j], vfr[0], vfr[1]);
                MMA16816(o[2 * p + 1], pa[j], vfr[2], vfr[3]);
            }
        }
        __syncthreads();
    }

    rs0 += __shfl_xor_sync(0xffffffffu, rs0, 1);
    rs0 += __shfl_xor_sync(0xffffffffu, rs0, 2);
    rs1 += __shfl_xor_sync(0xffffffffu, rs1, 1);
    rs1 += __shfl_xor_sync(0xffffffffu, rs1, 2);
    float i0 = 1.f / rs0, i1 = 1.f / rs1;

    const int r = lane >> 2, cc = (lane & 3) * 2;
    const int m0 = q0 + wid * 16 + r;
#pragma unroll
    for (int nt = 0; nt < 8; ++nt) {
        int col = h * DH + nt * 8 + cc;
        *(__nv_bfloat162*)(ctx + (size_t)m0 * DM + col)       = __floats2bfloat162_rn(o[nt][0] * i0, o[nt][1] * i0);
        *(__nv_bfloat162*)(ctx + (size_t)(m0 + 8) * DM + col) = __floats2bfloat162_rn(o[nt][2] * i1, o[nt][3] * i1);
    }
}

// ============================================================================
// LayerNorm: one block (128 thr) per row; float4 + warp shuffles.
// ============================================================================
__global__ void __launch_bounds__(128) ln_kernel(
    const float* __restrict__ X, const float* __restrict__ gamma,
    const float* __restrict__ beta, float* __restrict__ out)
{
    __shared__ float ws[4], ws2[4];
    const int row = blockIdx.x, t = threadIdx.x, lane = t & 31, w = t >> 5;
    float4 x = ((const float4*)(X + (size_t)row * DM))[t];

    float s = x.x + x.y + x.z + x.w;
#pragma unroll
    for (int o = 16; o > 0; o >>= 1) s += __shfl_xor_sync(0xffffffffu, s, o);
    if (lane == 0) ws[w] = s;
    __syncthreads();
    float mean = (ws[0] + ws[1] + ws[2] + ws[3]) * (1.f / DM);

    float d0 = x.x - mean, d1 = x.y - mean, d2 = x.z - mean, d3 = x.w - mean;
    float v = d0 * d0 + d1 * d1 + d2 * d2 + d3 * d3;
#pragma unroll
    for (int o = 16; o > 0; o >>= 1) v += __shfl_xor_sync(0xffffffffu, v, o);
    if (lane == 0) ws2[w] = v;
    __syncthreads();
    float rstd = rsqrtf((ws2[0] + ws2[1] + ws2[2] + ws2[3]) * (1.f / DM) + 1e-5f);

    float4 g = ((const float4*)gamma)[t];
    float4 b = ((const float4*)beta)[t];
    float4 o4 = make_float4(d0 * rstd * g.x + b.x, d1 * rstd * g.y + b.y,
                            d2 * rstd * g.z + b.z, d3 * rstd * g.w + b.w);
    ((float4*)(out + (size_t)row * DM))[t] = o4;
}

// ============================================================================
extern "C" void kernel_launch(void* const* d_in, const int* in_sizes, int n_in,
                              void* d_out, int out_size)
{
    const float* Q    = (const float*)d_in[0];
    const float* K    = (const float*)d_in[1];
    const float* V    = (const float*)d_in[2];
    const float* WQ   = (const float*)d_in[3];
    const float* bQ   = (const float*)d_in[4];
    const float* WK   = (const float*)d_in[5];
    const float* bK   = (const float*)d_in[6];
    const float* WV   = (const float*)d_in[7];
    const float* bV   = (const float*)d_in[8];
    const float* WO   = (const float*)d_in[9];
    const float* bO   = (const float*)d_in[10];
    const float* gamma= (const float*)d_in[11];
    const float* beta = (const float*)d_in[12];
    float* out = (float*)d_out;

    __nv_bfloat16 *Qb, *Kb, *Vb, *Wq, *Wk, *Wv, *Wo, *Qp, *Kp, *Vp, *ctxb;
    float* tmp;
    cudaGetSymbolAddress((void**)&Qb, g_Qb);
    cudaGetSymbolAddress((void**)&Kb, g_Kb);
    cudaGetSymbolAddress((void**)&Vb, g_Vb);
    cudaGetSymbolAddress((void**)&Wq, g_Wq);
    cudaGetSymbolAddress((void**)&Wk, g_Wk);
    cudaGetSymbolAddress((void**)&Wv, g_Wv);
    cudaGetSymbolAddress((void**)&Wo, g_Wo);
    cudaGetSymbolAddress((void**)&Qp, g_Qp);
    cudaGetSymbolAddress((void**)&Kp, g_Kp);
    cudaGetSymbolAddress((void**)&Vp, g_Vp);
    cudaGetSymbolAddress((void**)&ctxb, g_ctxb);
    cudaGetSymbolAddress((void**)&tmp, g_tmp);

    const int GEMM_SMEM  = 4 * 128 * TSTRIDE * 2;   // 73728
    const int FLASH_SMEM = 5 * 128 * TSTRIDE * 2;   // 92160
    cudaFuncSetAttribute(gemm_mma<0>, cudaFuncAttributeMaxDynamicSharedMemorySize, GEMM_SMEM);
    cudaFuncSetAttribute(gemm_mma<1>, cudaFuncAttributeMaxDynamicSharedMemorySize, GEMM_SMEM);
    cudaFuncSetAttribute(flash_mma,   cudaFuncAttributeMaxDynamicSharedMemorySize, FLASH_SMEM);

    const int n_in4 = NSEQ * DM / 4, n_w4 = DM * DM / 4;
    cvt_kernel<<<n_in4 / 256, 256>>>(Q, Qb, n_in4);
    cvt_kernel<<<n_in4 / 256, 256>>>(K, Kb, n_in4);
    cvt_kernel<<<n_in4 / 256, 256>>>(V, Vb, n_in4);
    cvt_kernel<<<n_w4 / 256, 256>>>(WQ, Wq, n_w4);
    cvt_kernel<<<n_w4 / 256, 256>>>(WK, Wk, n_w4);
    cvt_kernel<<<n_w4 / 256, 256>>>(WV, Wv, n_w4);
    cvt_kernel<<<n_w4 / 256, 256>>>(WO, Wo, n_w4);

    dim3 gg(DM / 128, NSEQ / 128);   // (4, 32)
    const float QSCALE = 0.125f * 1.44269504088896340736f;  // fold log2e into Q
    gemm_mma<0><<<gg, 256, GEMM_SMEM>>>(Qb, Wq, bQ, nullptr, Qp, QSCALE);
    gemm_mma<0><<<gg, 256, GEMM_SMEM>>>(Kb, Wk, bK, nullptr, Kp, 1.0f);
    gemm_mma<0><<<gg, 256, GEMM_SMEM>>>(Vb, Wv, bV, nullptr, Vp, 1.0f);

    flash_mma<<<dim3(NSEQ / 128, NH), 256, FLASH_SMEM>>>(Qp, Kp, Vp, ctxb);

    gemm_mma<1><<<gg, 256, GEMM_SMEM>>>(ctxb, Wo, bO, Q, tmp, 1.0f);

    ln_kernel<<<NSEQ, 128>>>(tmp, gamma, beta, out);
}

// round 13
// speedup vs baseline: 1.0391x; 1.0364x over previous
#include <cuda_runtime.h>
#include <cuda_bf16.h>
#include <cstdint>
#include <math.h>

#define NSEQ 4096
#define DM   512
#define NH   8
#define DH   64
#define TSTRIDE 72   // smem row stride in elements (144B): 16B-aligned, ldmatrix conflict-free

// ---------------- static scratch ----------------
__device__ __nv_bfloat16 g_Qb[NSEQ * DM];
__device__ __nv_bfloat16 g_Kb[NSEQ * DM];
__device__ __nv_bfloat16 g_Vb[NSEQ * DM];
__device__ __nv_bfloat16 g_Wq[DM * DM];
__device__ __nv_bfloat16 g_Wk[DM * DM];
__device__ __nv_bfloat16 g_Wv[DM * DM];
__device__ __nv_bfloat16 g_Wo[DM * DM];
__device__ __nv_bfloat16 g_Qp[NSEQ * DM];   // projected Q, pre-scaled by log2(e)/8
__device__ __nv_bfloat16 g_Kp[NSEQ * DM];
__device__ __nv_bfloat16 g_Vp[NSEQ * DM];
__device__ __nv_bfloat16 g_ctxb[NSEQ * DM];
__device__ float         g_tmp[NSEQ * DM];

// ---------------- helpers ----------------
__device__ __forceinline__ uint32_t smem_u32(const void* p) {
    uint32_t a;
    asm("{ .reg .u64 t; cvta.to.shared.u64 t, %1; cvt.u32.u64 %0, t; }" : "=r"(a) : "l"(p));
    return a;
}

// single-instruction MUFU.EX2 regardless of compiler math flags
__device__ __forceinline__ float ex2_fast(float x) {
    float y;
    asm("ex2.approx.ftz.f32 %0, %1;" : "=f"(y) : "f"(x));
    return y;
}

#define LDSM4(R, addr) \
    asm volatile("ldmatrix.sync.aligned.m8n8.x4.shared.b16 {%0,%1,%2,%3}, [%4];" \
        : "=r"((R)[0]), "=r"((R)[1]), "=r"((R)[2]), "=r"((R)[3]) : "r"(addr))

#define LDSM4T(R, addr) \
    asm volatile("ldmatrix.sync.aligned.m8n8.x4.trans.shared.b16 {%0,%1,%2,%3}, [%4];" \
        : "=r"((R)[0]), "=r"((R)[1]), "=r"((R)[2]), "=r"((R)[3]) : "r"(addr))

#define MMA16816(C, A, B0, B1) \
    asm volatile("mma.sync.aligned.m16n8k16.row.col.f32.bf16.bf16.f32 " \
        "{%0,%1,%2,%3},{%4,%5,%6,%7},{%8,%9},{%0,%1,%2,%3};" \
        : "+f"((C)[0]), "+f"((C)[1]), "+f"((C)[2]), "+f"((C)[3]) \
        : "r"((A)[0]), "r"((A)[1]), "r"((A)[2]), "r"((A)[3]), "r"(B0), "r"(B1))

#define CPA16(dst, src) \
    asm volatile("cp.async.cg.shared.global [%0], [%1], 16;" :: "r"(dst), "l"(src))
#define CPC() asm volatile("cp.async.commit_group;" ::: "memory")
#define CPW(n) asm volatile("cp.async.wait_group %0;" :: "n"(n) : "memory")

__device__ __forceinline__ uint32_t packbf(float a, float b) {
    __nv_bfloat162 t = __floats2bfloat162_rn(a, b);
    return *reinterpret_cast<uint32_t*>(&t);
}

// ============================================================================
// fp32 -> bf16 converts: 2 launches total.
// cvt_in:  grid (2048, 3) covers Q,K,V   (2048*256 = 524288 float4 exactly)
// cvt_w:   grid (256, 4)  covers Wq,Wk,Wv,Wo (256*256 = 65536 float4 exactly)
// ============================================================================
__global__ void __launch_bounds__(256) cvt_in_kernel(
    const float4* __restrict__ q, const float4* __restrict__ k, const float4* __restrict__ v,
    uint2* __restrict__ qo, uint2* __restrict__ ko, uint2* __restrict__ vo)
{
    const float4* src = (blockIdx.y == 0) ? q : (blockIdx.y == 1) ? k : v;
    uint2* dst        = (blockIdx.y == 0) ? qo : (blockIdx.y == 1) ? ko : vo;
    int i = blockIdx.x * 256 + threadIdx.x;
    float4 x = src[i];
    uint2 o; o.x = packbf(x.x, x.y); o.y = packbf(x.z, x.w);
    dst[i] = o;
}

__global__ void __launch_bounds__(256) cvt_w_kernel(
    const float4* __restrict__ w0, const float4* __restrict__ w1,
    const float4* __restrict__ w2, const float4* __restrict__ w3,
    uint2* __restrict__ o0, uint2* __restrict__ o1,
    uint2* __restrict__ o2, uint2* __restrict__ o3)
{
    const float4* src = (blockIdx.y == 0) ? w0 : (blockIdx.y == 1) ? w1 : (blockIdx.y == 2) ? w2 : w3;
    uint2* dst        = (blockIdx.y == 0) ? o0 : (blockIdx.y == 1) ? o1 : (blockIdx.y == 2) ? o2 : o3;
    int i = blockIdx.x * 256 + threadIdx.x;
    float4 x = src[i];
    uint2 o; o.x = packbf(x.x, x.y); o.y = packbf(x.z, x.w);
    dst[i] = o;
}

// ============================================================================
// GEMM: C[4096,512] = A[4096,512] @ W[512,512]^T, bf16 mma.sync.
// Epilogue: v = (acc + bias[n]) * scale;  RESID=1 adds fp32 R and stores fp32,
// RESID=0 stores bf16. Block 128x128, K-chunk 64, 8 warps (4Mx2N, 32x64 each).
// ============================================================================
template<int RESID>
__global__ void __launch_bounds__(256) gemm_mma(
    const __nv_bfloat16* __restrict__ A, const __nv_bfloat16* __restrict__ W,
    const float* __restrict__ bias, const float* __restrict__ R,
    void* __restrict__ Cout, float scale)
{
    extern __shared__ __align__(16) __nv_bfloat16 sm[];
    __nv_bfloat16* sA = sm;                       // [2][128][TSTRIDE]
    __nv_bfloat16* sB = sm + 2 * 128 * TSTRIDE;   // [2][128][TSTRIDE]
    const int tid = threadIdx.x, lane = tid & 31, wid = tid >> 5;
    const int mb = blockIdx.y * 128, nb = blockIdx.x * 128;
    const int wm = wid & 3, wn = wid >> 2;

    const int lrow = tid >> 1, lcol = (tid & 1) * 32;
    const __nv_bfloat16* gA = A + (size_t)(mb + lrow) * DM + lcol;
    const __nv_bfloat16* gB = W + (size_t)(nb + lrow) * DM + lcol;
    const uint32_t sAb = smem_u32(sA) + (lrow * TSTRIDE + lcol) * 2;
    const uint32_t sBb = smem_u32(sB) + (lrow * TSTRIDE + lcol) * 2;
    const uint32_t BUF = 128 * TSTRIDE * 2;

    float acc[2][8][4];
#pragma unroll
    for (int a = 0; a < 2; a++)
#pragma unroll
        for (int b = 0; b < 8; b++)
#pragma unroll
            for (int c = 0; c < 4; c++) acc[a][b][c] = 0.f;

#pragma unroll
    for (int j = 0; j < 4; j++) { CPA16(sAb + j * 16, gA + j * 8); CPA16(sBb + j * 16, gB + j * 8); }
    CPC();

    for (int it = 0; it < 8; ++it) {
        if (it < 7) {
            const __nv_bfloat16* a1 = gA + (it + 1) * 64;
            const __nv_bfloat16* b1 = gB + (it + 1) * 64;
            uint32_t da = sAb + ((it + 1) & 1) * BUF, db = sBb + ((it + 1) & 1) * BUF;
#pragma unroll
            for (int j = 0; j < 4; j++) { CPA16(da + j * 16, a1 + j * 8); CPA16(db + j * 16, b1 + j * 8); }
            CPC();
            CPW(1);
        } else {
            CPW(0);
        }
        __syncthreads();

        const uint32_t bA = smem_u32(sA) + (it & 1) * BUF;
        const uint32_t bB = smem_u32(sB) + (it & 1) * BUF;
#pragma unroll
        for (int ks = 0; ks < 4; ++ks) {
            uint32_t afr[2][4];
#pragma unroll
            for (int mt = 0; mt < 2; ++mt) {
                uint32_t ad = bA + ((wm * 32 + mt * 16 + ((lane >> 3) & 1) * 8 + (lane & 7)) * TSTRIDE
                                   + ks * 16 + (lane >> 4) * 8) * 2;
                LDSM4(afr[mt], ad);
            }
#pragma unroll
            for (int p = 0; p < 4; ++p) {
                uint32_t bfr[4];
                uint32_t bd = bB + ((wn * 64 + p * 16 + (lane >> 4) * 8 + (lane & 7)) * TSTRIDE
                                   + ks * 16 + ((lane >> 3) & 1) * 8) * 2;
                LDSM4(bfr, bd);
#pragma unroll
                for (int mt = 0; mt < 2; ++mt) {
                    MMA16816(acc[mt][2 * p],     afr[mt], bfr[0], bfr[1]);
                    MMA16816(acc[mt][2 * p + 1], afr[mt], bfr[2], bfr[3]);
                }
            }
        }
        __syncthreads();
    }

    const int r = lane >> 2, cc = (lane & 3) * 2;
#pragma unroll
    for (int mt = 0; mt < 2; ++mt) {
#pragma unroll
        for (int nt = 0; nt < 8; ++nt) {
            int m0 = mb + wm * 32 + mt * 16 + r;
            int n  = nb + wn * 64 + nt * 8 + cc;
            float b0 = bias[n], b1 = bias[n + 1];
            float v00 = (acc[mt][nt][0] + b0) * scale;
            float v01 = (acc[mt][nt][1] + b1) * scale;
            float v10 = (acc[mt][nt][2] + b0) * scale;
            float v11 = (acc[mt][nt][3] + b1) * scale;
            if (RESID) {
                const float* r0 = R + (size_t)m0 * DM + n;
                const float* r1 = R + (size_t)(m0 + 8) * DM + n;
                float2 o0 = make_float2(v00 + r0[0], v01 + r0[1]);
                float2 o1 = make_float2(v10 + r1[0], v11 + r1[1]);
                *(float2*)((float*)Cout + (size_t)m0 * DM + n)       = o0;
                *(float2*)((float*)Cout + (size_t)(m0 + 8) * DM + n) = o1;
            } else {
                *(__nv_bfloat162*)((__nv_bfloat16*)Cout + (size_t)m0 * DM + n)       = __floats2bfloat162_rn(v00, v01);
                *(__nv_bfloat162*)((__nv_bfloat16*)Cout + (size_t)(m0 + 8) * DM + n) = __floats2bfloat162_rn(v10, v11);
            }
        }
    }
}

// ============================================================================
// Flash attention, mma.sync. Block = 256 thr = 128 queries x 1 head.
// Warp w owns q-rows w*16..w*16+15 and all 128 keys of each tile: softmax is
// warp-local; S accumulators convert in-register to P a-frags. No-max softmax
// (ex2.approx; log2e/8 folded into Q projection). V via ldmatrix.trans.
// (Identical to R12's measured-best kernel.)
// ============================================================================
__global__ void __launch_bounds__(256) flash_mma(
    const __nv_bfloat16* __restrict__ Qp, const __nv_bfloat16* __restrict__ Kp,
    const __nv_bfloat16* __restrict__ Vp, __nv_bfloat16* __restrict__ ctx)
{
    extern __shared__ __align__(16) __nv_bfloat16 sm[];
    __nv_bfloat16* sQ = sm;                       // [128][TSTRIDE]
    __nv_bfloat16* sK = sm + 128 * TSTRIDE;       // [2][128][TSTRIDE]
    __nv_bfloat16* sV = sK + 2 * 128 * TSTRIDE;   // [2][128][TSTRIDE]
    const int tid = threadIdx.x, lane = tid & 31, wid = tid >> 5;
    const int h = blockIdx.y, q0 = blockIdx.x * 128;

    const int lrow = tid >> 1, lcol = (tid & 1) * 32;
    {
        const uint4* g = (const uint4*)(Qp + (size_t)(q0 + lrow) * DM + h * DH + lcol);
        uint4* s = (uint4*)(sQ + lrow * TSTRIDE + lcol);
#pragma unroll
        for (int j = 0; j < 4; j++) s[j] = g[j];
    }
    const __nv_bfloat16* gK = Kp + (size_t)lrow * DM + h * DH + lcol;
    const __nv_bfloat16* gV = Vp + (size_t)lrow * DM + h * DH + lcol;
    const uint32_t sKb = smem_u32(sK) + (lrow * TSTRIDE + lcol) * 2;
    const uint32_t sVb = smem_u32(sV) + (lrow * TSTRIDE + lcol) * 2;
    const uint32_t BUF = 128 * TSTRIDE * 2;
    const size_t TILE = (size_t)128 * DM;

#pragma unroll
    for (int j = 0; j < 4; j++) { CPA16(sKb + j * 16, gK + j * 8); CPA16(sVb + j * 16, gV + j * 8); }
    CPC();
    __syncthreads();

    uint32_t qf[4][4];
#pragma unroll
    for (int ks = 0; ks < 4; ks++) {
        uint32_t ad = smem_u32(sQ) + ((wid * 16 + ((lane >> 3) & 1) * 8 + (lane & 7)) * TSTRIDE
                                      + ks * 16 + (lane >> 4) * 8) * 2;
        LDSM4(qf[ks], ad);
    }

    float o[8][4];
#pragma unroll
    for (int a = 0; a < 8; a++)
#pragma unroll
        for (int b = 0; b < 4; b++) o[a][b] = 0.f;
    float rs0 = 0.f, rs1 = 0.f;

    for (int kt = 0; kt < 32; ++kt) {
        if (kt < 31) {
            const __nv_bfloat16* k1 = gK + (kt + 1) * TILE;
            const __nv_bfloat16* v1 = gV + (kt + 1) * TILE;
            uint32_t dk = sKb + ((kt + 1) & 1) * BUF, dv = sVb + ((kt + 1) & 1) * BUF;
#pragma unroll
            for (int j = 0; j < 4; j++) { CPA16(dk + j * 16, k1 + j * 8); CPA16(dv + j * 16, v1 + j * 8); }
            CPC();
            CPW(1);
        } else {
            CPW(0);
        }
        __syncthreads();

        const uint32_t bK = smem_u32(sK) + (kt & 1) * BUF;
        const uint32_t bV = smem_u32(sV) + (kt & 1) * BUF;

        // S = Q @ K^T : per-warp 16 x 128
        float s[16][4];
#pragma unroll
        for (int a = 0; a < 16; a++)
#pragma unroll
            for (int b = 0; b < 4; b++) s[a][b] = 0.f;
#pragma unroll
        for (int ks = 0; ks < 4; ++ks) {
#pragma unroll
            for (int p = 0; p < 8; ++p) {
                uint32_t bfr[4];
                uint32_t bd = bK + ((p * 16 + (lane >> 4) * 8 + (lane & 7)) * TSTRIDE
                                   + ks * 16 + ((lane >> 3) & 1) * 8) * 2;
                LDSM4(bfr, bd);
                MMA16816(s[2 * p],     qf[ks], bfr[0], bfr[1]);
                MMA16816(s[2 * p + 1], qf[ks], bfr[2], bfr[3]);
            }
        }

        // exp2 (MUFU) + row-sum + pack into P a-frags
        uint32_t pa[8][4];
#pragma unroll
        for (int j = 0; j < 8; ++j) {
            float e00 = ex2_fast(s[2 * j][0]),     e01 = ex2_fast(s[2 * j][1]);
            float e10 = ex2_fast(s[2 * j][2]),     e11 = ex2_fast(s[2 * j][3]);
            float f00 = ex2_fast(s[2 * j + 1][0]), f01 = ex2_fast(s[2 * j + 1][1]);
            float f10 = ex2_fast(s[2 * j + 1][2]), f11 = ex2_fast(s[2 * j + 1][3]);
            rs0 += e00 + e01 + f00 + f01;
            rs1 += e10 + e11 + f10 + f11;
            pa[j][0] = packbf(e00, e01);
            pa[j][1] = packbf(e10, e11);
            pa[j][2] = packbf(f00, f01);
            pa[j][3] = packbf(f10, f11);
        }

        // O += P @ V
#pragma unroll
        for (int j = 0; j < 8; ++j) {
#pragma unroll
            for (int p = 0; p < 4; ++p) {
                uint32_t vfr[4];
                uint32_t vd = bV + ((j * 16 + ((lane >> 3) & 1) * 8 + (lane & 7)) * TSTRIDE
                                   + p * 16 + (lane >> 4) * 8) * 2;
                LDSM4T(vfr, vd);
                MMA16816(o[2 * p],     pa[j], vfr[0], vfr[1]);
                MMA16816(o[2 * p + 1], pa[j], vfr[2], vfr[3]);
            }
        }
        __syncthreads();
    }

    rs0 += __shfl_xor_sync(0xffffffffu, rs0, 1);
    rs0 += __shfl_xor_sync(0xffffffffu, rs0, 2);
    rs1 += __shfl_xor_sync(0xffffffffu, rs1, 1);
    rs1 += __shfl_xor_sync(0xffffffffu, rs1, 2);
    float i0 = 1.f / rs0, i1 = 1.f / rs1;

    const int r = lane >> 2, cc = (lane & 3) * 2;
    const int m0 = q0 + wid * 16 + r;
#pragma unroll
    for (int nt = 0; nt < 8; ++nt) {
        int col = h * DH + nt * 8 + cc;
        *(__nv_bfloat162*)(ctx + (size_t)m0 * DM + col)       = __floats2bfloat162_rn(o[nt][0] * i0, o[nt][1] * i0);
        *(__nv_bfloat162*)(ctx + (size_t)(m0 + 8) * DM + col) = __floats2bfloat162_rn(o[nt][2] * i1, o[nt][3] * i1);
    }
}

// ============================================================================
// LayerNorm: one block (128 thr) per row; float4 + warp shuffles.
// ============================================================================
__global__ void __launch_bounds__(128) ln_kernel(
    const float* __restrict__ X, const float* __restrict__ gamma,
    const float* __restrict__ beta, float* __restrict__ out)
{
    __shared__ float ws[4], ws2[4];
    const int row = blockIdx.x, t = threadIdx.x, lane = t & 31, w = t >> 5;
    float4 x = ((const float4*)(X + (size_t)row * DM))[t];

    float s = x.x + x.y + x.z + x.w;
#pragma unroll
    for (int o = 16; o > 0; o >>= 1) s += __shfl_xor_sync(0xffffffffu, s, o);
    if (lane == 0) ws[w] = s;
    __syncthreads();
    float mean = (ws[0] + ws[1] + ws[2] + ws[3]) * (1.f / DM);

    float d0 = x.x - mean, d1 = x.y - mean, d2 = x.z - mean, d3 = x.w - mean;
    float v = d0 * d0 + d1 * d1 + d2 * d2 + d3 * d3;
#pragma unroll
    for (int o = 16; o > 0; o >>= 1) v += __shfl_xor_sync(0xffffffffu, v, o);
    if (lane == 0) ws2[w] = v;
    __syncthreads();
    float rstd = rsqrtf((ws2[0] + ws2[1] + ws2[2] + ws2[3]) * (1.f / DM) + 1e-5f);

    float4 g = ((const float4*)gamma)[t];
    float4 b = ((const float4*)beta)[t];
    float4 o4 = make_float4(d0 * rstd * g.x + b.x, d1 * rstd * g.y + b.y,
                            d2 * rstd * g.z + b.z, d3 * rstd * g.w + b.w);
    ((float4*)(out + (size_t)row * DM))[t] = o4;
}

// ============================================================================
extern "C" void kernel_launch(void* const* d_in, const int* in_sizes, int n_in,
                              void* d_out, int out_size)
{
    const float* Q    = (const float*)d_in[0];
    const float* K    = (const float*)d_in[1];
    const float* V    = (const float*)d_in[2];
    const float* WQ   = (const float*)d_in[3];
    const float* bQ   = (const float*)d_in[4];
    const float* WK   = (const float*)d_in[5];
    const float* bK   = (const float*)d_in[6];
    const float* WV   = (const float*)d_in[7];
    const float* bV   = (const float*)d_in[8];
    const float* WO   = (const float*)d_in[9];
    const float* bO   = (const float*)d_in[10];
    const float* gamma= (const float*)d_in[11];
    const float* beta = (const float*)d_in[12];
    float* out = (float*)d_out;

    __nv_bfloat16 *Qb, *Kb, *Vb, *Wq, *Wk, *Wv, *Wo, *Qp, *Kp, *Vp, *ctxb;
    float* tmp;
    cudaGetSymbolAddress((void**)&Qb, g_Qb);
    cudaGetSymbolAddress((void**)&Kb, g_Kb);
    cudaGetSymbolAddress((void**)&Vb, g_Vb);
    cudaGetSymbolAddress((void**)&Wq, g_Wq);
    cudaGetSymbolAddress((void**)&Wk, g_Wk);
    cudaGetSymbolAddress((void**)&Wv, g_Wv);
    cudaGetSymbolAddress((void**)&Wo, g_Wo);
    cudaGetSymbolAddress((void**)&Qp, g_Qp);
    cudaGetSymbolAddress((void**)&Kp, g_Kp);
    cudaGetSymbolAddress((void**)&Vp, g_Vp);
    cudaGetSymbolAddress((void**)&ctxb, g_ctxb);
    cudaGetSymbolAddress((void**)&tmp, g_tmp);

    const int GEMM_SMEM  = 4 * 128 * TSTRIDE * 2;   // 73728
    const int FLASH_SMEM = 5 * 128 * TSTRIDE * 2;   // 92160
    cudaFuncSetAttribute(gemm_mma<0>, cudaFuncAttributeMaxDynamicSharedMemorySize, GEMM_SMEM);
    cudaFuncSetAttribute(gemm_mma<1>, cudaFuncAttributeMaxDynamicSharedMemorySize, GEMM_SMEM);
    cudaFuncSetAttribute(flash_mma,   cudaFuncAttributeMaxDynamicSharedMemorySize, FLASH_SMEM);

    // launch 0: convert Q,K,V inputs (3 segments, exact-fit grid)
    cvt_in_kernel<<<dim3(2048, 3), 256>>>(
        (const float4*)Q, (const float4*)K, (const float4*)V,
        (uint2*)Qb, (uint2*)Kb, (uint2*)Vb);
    // launch 1: convert 4 weight matrices
    cvt_w_kernel<<<dim3(256, 4), 256>>>(
        (const float4*)WQ, (const float4*)WK, (const float4*)WV, (const float4*)WO,
        (uint2*)Wq, (uint2*)Wk, (uint2*)Wv, (uint2*)Wo);

    dim3 gg(DM / 128, NSEQ / 128);   // (4, 32)
    const float QSCALE = 0.125f * 1.44269504088896340736f;  // fold log2e into Q
    // launches 2-4
    gemm_mma<0><<<gg, 256, GEMM_SMEM>>>(Qb, Wq, bQ, nullptr, Qp, QSCALE);
    gemm_mma<0><<<gg, 256, GEMM_SMEM>>>(Kb, Wk, bK, nullptr, Kp, 1.0f);
    gemm_mma<0><<<gg, 256, GEMM_SMEM>>>(Vb, Wv, bV, nullptr, Vp, 1.0f);

    // launch 5 (ncu sample target)
    flash_mma<<<dim3(NSEQ / 128, NH), 256, FLASH_SMEM>>>(Qp, Kp, Vp, ctxb);

    // launch 6
    gemm_mma<1><<<gg, 256, GEMM_SMEM>>>(ctxb, Wo, bO, Q, tmp, 1.0f);

    // launch 7
    ln_kernel<<<NSEQ, 128>>>(tmp, gamma, beta, out);
}

// round 14
// speedup vs baseline: 1.0628x; 1.0228x over previous
#include <cuda_runtime.h>
#include <cuda_bf16.h>
#include <cstdint>
#include <math.h>

#define NSEQ 4096
#define DM   512
#define NH   8
#define DH   64
#define TSTRIDE 72   // smem row stride in elements (144B): 16B-aligned, ldmatrix conflict-free

// ---------------- static scratch ----------------
__device__ __nv_bfloat16 g_Qb[NSEQ * DM];
__device__ __nv_bfloat16 g_Kb[NSEQ * DM];
__device__ __nv_bfloat16 g_Vb[NSEQ * DM];
__device__ __nv_bfloat16 g_Wq[DM * DM];
__device__ __nv_bfloat16 g_Wk[DM * DM];
__device__ __nv_bfloat16 g_Wv[DM * DM];
__device__ __nv_bfloat16 g_Wo[DM * DM];
__device__ __nv_bfloat16 g_Qp[NSEQ * DM];   // projected Q, pre-scaled by log2(e)/8
__device__ __nv_bfloat16 g_Kp[NSEQ * DM];
__device__ __nv_bfloat16 g_Vp[NSEQ * DM];
__device__ __nv_bfloat16 g_ctxb[NSEQ * DM];
__device__ float         g_tmp[NSEQ * DM];

// ---------------- helpers ----------------
__device__ __forceinline__ uint32_t smem_u32(const void* p) {
    uint32_t a;
    asm("{ .reg .u64 t; cvta.to.shared.u64 t, %1; cvt.u32.u64 %0, t; }" : "=r"(a) : "l"(p));
    return a;
}

// single-instruction MUFU.EX2 regardless of compiler math flags
__device__ __forceinline__ float ex2_fast(float x) {
    float y;
    asm("ex2.approx.ftz.f32 %0, %1;" : "=f"(y) : "f"(x));
    return y;
}

#define LDSM4(R, addr) \
    asm volatile("ldmatrix.sync.aligned.m8n8.x4.shared.b16 {%0,%1,%2,%3}, [%4];" \
        : "=r"((R)[0]), "=r"((R)[1]), "=r"((R)[2]), "=r"((R)[3]) : "r"(addr))

#define LDSM4T(R, addr) \
    asm volatile("ldmatrix.sync.aligned.m8n8.x4.trans.shared.b16 {%0,%1,%2,%3}, [%4];" \
        : "=r"((R)[0]), "=r"((R)[1]), "=r"((R)[2]), "=r"((R)[3]) : "r"(addr))

#define MMA16816(C, A, B0, B1) \
    asm volatile("mma.sync.aligned.m16n8k16.row.col.f32.bf16.bf16.f32 " \
        "{%0,%1,%2,%3},{%4,%5,%6,%7},{%8,%9},{%0,%1,%2,%3};" \
        : "+f"((C)[0]), "+f"((C)[1]), "+f"((C)[2]), "+f"((C)[3]) \
        : "r"((A)[0]), "r"((A)[1]), "r"((A)[2]), "r"((A)[3]), "r"(B0), "r"(B1))

#define CPA16(dst, src) \
    asm volatile("cp.async.cg.shared.global [%0], [%1], 16;" :: "r"(dst), "l"(src))
#define CPC() asm volatile("cp.async.commit_group;" ::: "memory")
#define CPW(n) asm volatile("cp.async.wait_group %0;" :: "n"(n) : "memory")

__device__ __forceinline__ uint32_t packbf(float a, float b) {
    __nv_bfloat162 t = __floats2bfloat162_rn(a, b);
    return *reinterpret_cast<uint32_t*>(&t);
}

// ============================================================================
// fp32 -> bf16 converts: 2 launches total (identical to R13).
// ============================================================================
__global__ void __launch_bounds__(256) cvt_in_kernel(
    const float4* __restrict__ q, const float4* __restrict__ k, const float4* __restrict__ v,
    uint2* __restrict__ qo, uint2* __restrict__ ko, uint2* __restrict__ vo)
{
    const float4* src = (blockIdx.y == 0) ? q : (blockIdx.y == 1) ? k : v;
    uint2* dst        = (blockIdx.y == 0) ? qo : (blockIdx.y == 1) ? ko : vo;
    int i = blockIdx.x * 256 + threadIdx.x;
    float4 x = src[i];
    uint2 o; o.x = packbf(x.x, x.y); o.y = packbf(x.z, x.w);
    dst[i] = o;
}

__global__ void __launch_bounds__(256) cvt_w_kernel(
    const float4* __restrict__ w0, const float4* __restrict__ w1,
    const float4* __restrict__ w2, const float4* __restrict__ w3,
    uint2* __restrict__ o0, uint2* __restrict__ o1,
    uint2* __restrict__ o2, uint2* __restrict__ o3)
{
    const float4* src = (blockIdx.y == 0) ? w0 : (blockIdx.y == 1) ? w1 : (blockIdx.y == 2) ? w2 : w3;
    uint2* dst        = (blockIdx.y == 0) ? o0 : (blockIdx.y == 1) ? o1 : (blockIdx.y == 2) ? o2 : o3;
    int i = blockIdx.x * 256 + threadIdx.x;
    float4 x = src[i];
    uint2 o; o.x = packbf(x.x, x.y); o.y = packbf(x.z, x.w);
    dst[i] = o;
}

// ============================================================================
// GEMM mainloop core (bit-identical to R13's measured mainloop), factored so
// the fused-QKV kernel and the outproj kernel share codegen.
// Block 128x128, K-chunk 64, 8 warps (4Mx2N, 32x64 each), cp.async dbl-buf.
// ============================================================================
__device__ __forceinline__ void gemm_core(
    const __nv_bfloat16* __restrict__ A, const __nv_bfloat16* __restrict__ W,
    int mb, int nb, __nv_bfloat16* sm, float acc[2][8][4])
{
    __nv_bfloat16* sA = sm;                       // [2][128][TSTRIDE]
    __nv_bfloat16* sB = sm + 2 * 128 * TSTRIDE;   // [2][128][TSTRIDE]
    const int tid = threadIdx.x, lane = tid & 31, wid = tid >> 5;
    const int wm = wid & 3, wn = wid >> 2;

    const int lrow = tid >> 1, lcol = (tid & 1) * 32;
    const __nv_bfloat16* gA = A + (size_t)(mb + lrow) * DM + lcol;
    const __nv_bfloat16* gB = W + (size_t)(nb + lrow) * DM + lcol;
    const uint32_t sAb = smem_u32(sA) + (lrow * TSTRIDE + lcol) * 2;
    const uint32_t sBb = smem_u32(sB) + (lrow * TSTRIDE + lcol) * 2;
    const uint32_t BUF = 128 * TSTRIDE * 2;

#pragma unroll
    for (int j = 0; j < 4; j++) { CPA16(sAb + j * 16, gA + j * 8); CPA16(sBb + j * 16, gB + j * 8); }
    CPC();

    for (int it = 0; it < 8; ++it) {
        if (it < 7) {
            const __nv_bfloat16* a1 = gA + (it + 1) * 64;
            const __nv_bfloat16* b1 = gB + (it + 1) * 64;
            uint32_t da = sAb + ((it + 1) & 1) * BUF, db = sBb + ((it + 1) & 1) * BUF;
#pragma unroll
            for (int j = 0; j < 4; j++) { CPA16(da + j * 16, a1 + j * 8); CPA16(db + j * 16, b1 + j * 8); }
            CPC();
            CPW(1);
        } else {
            CPW(0);
        }
        __syncthreads();

        const uint32_t bA = smem_u32(sA) + (it & 1) * BUF;
        const uint32_t bB = smem_u32(sB) + (it & 1) * BUF;
#pragma unroll
        for (int ks = 0; ks < 4; ++ks) {
            uint32_t afr[2][4];
#pragma unroll
            for (int mt = 0; mt < 2; ++mt) {
                uint32_t ad = bA + ((wm * 32 + mt * 16 + ((lane >> 3) & 1) * 8 + (lane & 7)) * TSTRIDE
                                   + ks * 16 + (lane >> 4) * 8) * 2;
                LDSM4(afr[mt], ad);
            }
#pragma unroll
            for (int p = 0; p < 4; ++p) {
                uint32_t bfr[4];
                uint32_t bd = bB + ((wn * 64 + p * 16 + (lane >> 4) * 8 + (lane & 7)) * TSTRIDE
                                   + ks * 16 + ((lane >> 3) & 1) * 8) * 2;
                LDSM4(bfr, bd);
#pragma unroll
                for (int mt = 0; mt < 2; ++mt) {
                    MMA16816(acc[mt][2 * p],     afr[mt], bfr[0], bfr[1]);
                    MMA16816(acc[mt][2 * p + 1], afr[mt], bfr[2], bfr[3]);
                }
            }
        }
        __syncthreads();
    }
}

// ---- fused QKV projection: gridDim.z selects {Q,K,V}; bf16 output ----
__global__ void __launch_bounds__(256) qkv_gemm(
    const __nv_bfloat16* __restrict__ Qb, const __nv_bfloat16* __restrict__ Kb,
    const __nv_bfloat16* __restrict__ Vb,
    const __nv_bfloat16* __restrict__ Wq, const __nv_bfloat16* __restrict__ Wk,
    const __nv_bfloat16* __restrict__ Wv,
    const float* __restrict__ bq, const float* __restrict__ bk, const float* __restrict__ bv,
    __nv_bfloat16* __restrict__ Qp, __nv_bfloat16* __restrict__ Kp, __nv_bfloat16* __restrict__ Vp,
    float qscale)
{
    extern __shared__ __align__(16) __nv_bfloat16 sm[];
    const int z = blockIdx.z;
    const __nv_bfloat16* A = (z == 0) ? Qb : (z == 1) ? Kb : Vb;
    const __nv_bfloat16* W = (z == 0) ? Wq : (z == 1) ? Wk : Wv;
    const float* bias      = (z == 0) ? bq : (z == 1) ? bk : bv;
    __nv_bfloat16* C       = (z == 0) ? Qp : (z == 1) ? Kp : Vp;
    const float scale      = (z == 0) ? qscale : 1.0f;
    const int mb = blockIdx.y * 128, nb = blockIdx.x * 128;

    float acc[2][8][4];
#pragma unroll
    for (int a = 0; a < 2; a++)
#pragma unroll
        for (int b = 0; b < 8; b++)
#pragma unroll
            for (int c = 0; c < 4; c++) acc[a][b][c] = 0.f;

    gemm_core(A, W, mb, nb, sm, acc);

    const int lane = threadIdx.x & 31, wid = threadIdx.x >> 5;
    const int wm = wid & 3, wn = wid >> 2;
    const int r = lane >> 2, cc = (lane & 3) * 2;
#pragma unroll
    for (int mt = 0; mt < 2; ++mt) {
#pragma unroll
        for (int nt = 0; nt < 8; ++nt) {
            int m0 = mb + wm * 32 + mt * 16 + r;
            int n  = nb + wn * 64 + nt * 8 + cc;
            float b0 = bias[n], b1 = bias[n + 1];
            *(__nv_bfloat162*)(C + (size_t)m0 * DM + n) =
                __floats2bfloat162_rn((acc[mt][nt][0] + b0) * scale, (acc[mt][nt][1] + b1) * scale);
            *(__nv_bfloat162*)(C + (size_t)(m0 + 8) * DM + n) =
                __floats2bfloat162_rn((acc[mt][nt][2] + b0) * scale, (acc[mt][nt][3] + b1) * scale);
        }
    }
}

// ---- output projection: bf16 ctx @ Wo^T + bias + fp32 residual, fp32 out ----
__global__ void __launch_bounds__(256) outproj_gemm(
    const __nv_bfloat16* __restrict__ A, const __nv_bfloat16* __restrict__ W,
    const float* __restrict__ bias, const float* __restrict__ R,
    float* __restrict__ C)
{
    extern __shared__ __align__(16) __nv_bfloat16 sm[];
    const int mb = blockIdx.y * 128, nb = blockIdx.x * 128;

    float acc[2][8][4];
#pragma unroll
    for (int a = 0; a < 2; a++)
#pragma unroll
        for (int b = 0; b < 8; b++)
#pragma unroll
            for (int c = 0; c < 4; c++) acc[a][b][c] = 0.f;

    gemm_core(A, W, mb, nb, sm, acc);

    const int lane = threadIdx.x & 31, wid = threadIdx.x >> 5;
    const int wm = wid & 3, wn = wid >> 2;
    const int r = lane >> 2, cc = (lane & 3) * 2;
#pragma unroll
    for (int mt = 0; mt < 2; ++mt) {
#pragma unroll
        for (int nt = 0; nt < 8; ++nt) {
            int m0 = mb + wm * 32 + mt * 16 + r;
            int n  = nb + wn * 64 + nt * 8 + cc;
            float b0 = bias[n], b1 = bias[n + 1];
            const float* r0 = R + (size_t)m0 * DM + n;
            const float* r1 = R + (size_t)(m0 + 8) * DM + n;
            *(float2*)(C + (size_t)m0 * DM + n) =
                make_float2(acc[mt][nt][0] + b0 + r0[0], acc[mt][nt][1] + b1 + r0[1]);
            *(float2*)(C + (size_t)(m0 + 8) * DM + n) =
                make_float2(acc[mt][nt][2] + b0 + r1[0], acc[mt][nt][3] + b1 + r1[1]);
        }
    }
}

// ============================================================================
// Flash attention, mma.sync (identical to R12/R13's measured-best kernel).
// ============================================================================
__global__ void __launch_bounds__(256) flash_mma(
    const __nv_bfloat16* __restrict__ Qp, const __nv_bfloat16* __restrict__ Kp,
    const __nv_bfloat16* __restrict__ Vp, __nv_bfloat16* __restrict__ ctx)
{
    extern __shared__ __align__(16) __nv_bfloat16 sm[];
    __nv_bfloat16* sQ = sm;                       // [128][TSTRIDE]
    __nv_bfloat16* sK = sm + 128 * TSTRIDE;       // [2][128][TSTRIDE]
    __nv_bfloat16* sV = sK + 2 * 128 * TSTRIDE;   // [2][128][TSTRIDE]
    const int tid = threadIdx.x, lane = tid & 31, wid = tid >> 5;
    const int h = blockIdx.y, q0 = blockIdx.x * 128;

    const int lrow = tid >> 1, lcol = (tid & 1) * 32;
    {
        const uint4* g = (const uint4*)(Qp + (size_t)(q0 + lrow) * DM + h * DH + lcol);
        uint4* s = (uint4*)(sQ + lrow * TSTRIDE + lcol);
#pragma unroll
        for (int j = 0; j < 4; j++) s[j] = g[j];
    }
    const __nv_bfloat16* gK = Kp + (size_t)lrow * DM + h * DH + lcol;
    const __nv_bfloat16* gV = Vp + (size_t)lrow * DM + h * DH + lcol;
    const uint32_t sKb = smem_u32(sK) + (lrow * TSTRIDE + lcol) * 2;
    const uint32_t sVb = smem_u32(sV) + (lrow * TSTRIDE + lcol) * 2;
    const uint32_t BUF = 128 * TSTRIDE * 2;
    const size_t TILE = (size_t)128 * DM;

#pragma unroll
    for (int j = 0; j < 4; j++) { CPA16(sKb + j * 16, gK + j * 8); CPA16(sVb + j * 16, gV + j * 8); }
    CPC();
    __syncthreads();

    uint32_t qf[4][4];
#pragma unroll
    for (int ks = 0; ks < 4; ks++) {
        uint32_t ad = smem_u32(sQ) + ((wid * 16 + ((lane >> 3) & 1) * 8 + (lane & 7)) * TSTRIDE
                                      + ks * 16 + (lane >> 4) * 8) * 2;
        LDSM4(qf[ks], ad);
    }

    float o[8][4];
#pragma unroll
    for (int a = 0; a < 8; a++)
#pragma unroll
        for (int b = 0; b < 4; b++) o[a][b] = 0.f;
    float rs0 = 0.f, rs1 = 0.f;

    for (int kt = 0; kt < 32; ++kt) {
        if (kt < 31) {
            const __nv_bfloat16* k1 = gK + (kt + 1) * TILE;
            const __nv_bfloat16* v1 = gV + (kt + 1) * TILE;
            uint32_t dk = sKb + ((kt + 1) & 1) * BUF, dv = sVb + ((kt + 1) & 1) * BUF;
#pragma unroll
            for (int j = 0; j < 4; j++) { CPA16(dk + j * 16, k1 + j * 8); CPA16(dv + j * 16, v1 + j * 8); }
            CPC();
            CPW(1);
        } else {
            CPW(0);
        }
        __syncthreads();

        const uint32_t bK = smem_u32(sK) + (kt & 1) * BUF;
        const uint32_t bV = smem_u32(sV) + (kt & 1) * BUF;

        // S = Q @ K^T : per-warp 16 x 128
        float s[16][4];
#pragma unroll
        for (int a = 0; a < 16; a++)
#pragma unroll
            for (int b = 0; b < 4; b++) s[a][b] = 0.f;
#pragma unroll
        for (int ks = 0; ks < 4; ++ks) {
#pragma unroll
            for (int p = 0; p < 8; ++p) {
                uint32_t bfr[4];
                uint32_t bd = bK + ((p * 16 + (lane >> 4) * 8 + (lane & 7)) * TSTRIDE
                                   + ks * 16 + ((lane >> 3) & 1) * 8) * 2;
                LDSM4(bfr, bd);
                MMA16816(s[2 * p],     qf[ks], bfr[0], bfr[1]);
                MMA16816(s[2 * p + 1], qf[ks], bfr[2], bfr[3]);
            }
        }

        // exp2 (MUFU) + row-sum + pack into P a-frags
        uint32_t pa[8][4];
#pragma unroll
        for (int j = 0; j < 8; ++j) {
            float e00 = ex2_fast(s[2 * j][0]),     e01 = ex2_fast(s[2 * j][1]);
            float e10 = ex2_fast(s[2 * j][2]),     e11 = ex2_fast(s[2 * j][3]);
            float f00 = ex2_fast(s[2 * j + 1][0]), f01 = ex2_fast(s[2 * j + 1][1]);
            float f10 = ex2_fast(s[2 * j + 1][2]), f11 = ex2_fast(s[2 * j + 1][3]);
            rs0 += e00 + e01 + f00 + f01;
            rs1 += e10 + e11 + f10 + f11;
            pa[j][0] = packbf(e00, e01);
            pa[j][1] = packbf(e10, e11);
            pa[j][2] = packbf(f00, f01);
            pa[j][3] = packbf(f10, f11);
        }

        // O += P @ V
#pragma unroll
        for (int j = 0; j < 8; ++j) {
#pragma unroll
            for (int p = 0; p < 4; ++p) {
                uint32_t vfr[4];
                uint32_t vd = bV + ((j * 16 + ((lane >> 3) & 1) * 8 + (lane & 7)) * TSTRIDE
                                   + p * 16 + (lane >> 4) * 8) * 2;
                LDSM4T(vfr, vd);
                MMA16816(o[2 * p],     pa[j], vfr[0], vfr[1]);
                MMA16816(o[2 * p + 1], pa[j], vfr[2], vfr[3]);
            }
        }
        __syncthreads();
    }

    rs0 += __shfl_xor_sync(0xffffffffu, rs0, 1);
    rs0 += __shfl_xor_sync(0xffffffffu, rs0, 2);
    rs1 += __shfl_xor_sync(0xffffffffu, rs1, 1);
    rs1 += __shfl_xor_sync(0xffffffffu, rs1, 2);
    float i0 = 1.f / rs0, i1 = 1.f / rs1;

    const int r = lane >> 2, cc = (lane & 3) * 2;
    const int m0 = q0 + wid * 16 + r;
#pragma unroll
    for (int nt = 0; nt < 8; ++nt) {
        int col = h * DH + nt * 8 + cc;
        *(__nv_bfloat162*)(ctx + (size_t)m0 * DM + col)       = __floats2bfloat162_rn(o[nt][0] * i0, o[nt][1] * i0);
        *(__nv_bfloat162*)(ctx + (size_t)(m0 + 8) * DM + col) = __floats2bfloat162_rn(o[nt][2] * i1, o[nt][3] * i1);
    }
}

// ============================================================================
// LayerNorm: one block (128 thr) per row; float4 + warp shuffles.
// ============================================================================
__global__ void __launch_bounds__(128) ln_kernel(
    const float* __restrict__ X, const float* __restrict__ gamma,
    const float* __restrict__ beta, float* __restrict__ out)
{
    __shared__ float ws[4], ws2[4];
    const int row = blockIdx.x, t = threadIdx.x, lane = t & 31, w = t >> 5;
    float4 x = ((const float4*)(X + (size_t)row * DM))[t];

    float s = x.x + x.y + x.z + x.w;
#pragma unroll
    for (int o = 16; o > 0; o >>= 1) s += __shfl_xor_sync(0xffffffffu, s, o);
    if (lane == 0) ws[w] = s;
    __syncthreads();
    float mean = (ws[0] + ws[1] + ws[2] + ws[3]) * (1.f / DM);

    float d0 = x.x - mean, d1 = x.y - mean, d2 = x.z - mean, d3 = x.w - mean;
    float v = d0 * d0 + d1 * d1 + d2 * d2 + d3 * d3;
#pragma unroll
    for (int o = 16; o > 0; o >>= 1) v += __shfl_xor_sync(0xffffffffu, v, o);
    if (lane == 0) ws2[w] = v;
    __syncthreads();
    float rstd = rsqrtf((ws2[0] + ws2[1] + ws2[2] + ws2[3]) * (1.f / DM) + 1e-5f);

    float4 g = ((const float4*)gamma)[t];
    float4 b = ((const float4*)beta)[t];
    float4 o4 = make_float4(d0 * rstd * g.x + b.x, d1 * rstd * g.y + b.y,
                            d2 * rstd * g.z + b.z, d3 * rstd * g.w + b.w);
    ((float4*)(out + (size_t)row * DM))[t] = o4;
}

// ============================================================================
extern "C" void kernel_launch(void* const* d_in, const int* in_sizes, int n_in,
                              void* d_out, int out_size)
{
    const float* Q    = (const float*)d_in[0];
    const float* K    = (const float*)d_in[1];
    const float* V    = (const float*)d_in[2];
    const float* WQ   = (const float*)d_in[3];
    const float* bQ   = (const float*)d_in[4];
    const float* WK   = (const float*)d_in[5];
    const float* bK   = (const float*)d_in[6];
    const float* WV   = (const float*)d_in[7];
    const float* bV   = (const float*)d_in[8];
    const float* WO   = (const float*)d_in[9];
    const float* bO   = (const float*)d_in[10];
    const float* gamma= (const float*)d_in[11];
    const float* beta = (const float*)d_in[12];
    float* out = (float*)d_out;

    __nv_bfloat16 *Qb, *Kb, *Vb, *Wq, *Wk, *Wv, *Wo, *Qp, *Kp, *Vp, *ctxb;
    float* tmp;
    cudaGetSymbolAddress((void**)&Qb, g_Qb);
    cudaGetSymbolAddress((void**)&Kb, g_Kb);
    cudaGetSymbolAddress((void**)&Vb, g_Vb);
    cudaGetSymbolAddress((void**)&Wq, g_Wq);
    cudaGetSymbolAddress((void**)&Wk, g_Wk);
    cudaGetSymbolAddress((void**)&Wv, g_Wv);
    cudaGetSymbolAddress((void**)&Wo, g_Wo);
    cudaGetSymbolAddress((void**)&Qp, g_Qp);
    cudaGetSymbolAddress((void**)&Kp, g_Kp);
    cudaGetSymbolAddress((void**)&Vp, g_Vp);
    cudaGetSymbolAddress((void**)&ctxb, g_ctxb);
    cudaGetSymbolAddress((void**)&tmp, g_tmp);

    const int GEMM_SMEM  = 4 * 128 * TSTRIDE * 2;   // 73728
    const int FLASH_SMEM = 5 * 128 * TSTRIDE * 2;   // 92160
    cudaFuncSetAttribute(qkv_gemm,     cudaFuncAttributeMaxDynamicSharedMemorySize, GEMM_SMEM);
    cudaFuncSetAttribute(outproj_gemm, cudaFuncAttributeMaxDynamicSharedMemorySize, GEMM_SMEM);
    cudaFuncSetAttribute(flash_mma,    cudaFuncAttributeMaxDynamicSharedMemorySize, FLASH_SMEM);

    // launch 0: convert Q,K,V inputs (3 segments, exact-fit grid)
    cvt_in_kernel<<<dim3(2048, 3), 256>>>(
        (const float4*)Q, (const float4*)K, (const float4*)V,
        (uint2*)Qb, (uint2*)Kb, (uint2*)Vb);
    // launch 1: convert 4 weight matrices
    cvt_w_kernel<<<dim3(256, 4), 256>>>(
        (const float4*)WQ, (const float4*)WK, (const float4*)WV, (const float4*)WO,
        (uint2*)Wq, (uint2*)Wk, (uint2*)Wv, (uint2*)Wo);

    const float QSCALE = 0.125f * 1.44269504088896340736f;  // fold log2e into Q
    // launch 2: all three projections co-scheduled (384 blocks, ~1.3 waves)
    dim3 gq(DM / 128, NSEQ / 128, 3);   // (4, 32, 3)
    qkv_gemm<<<gq, 256, GEMM_SMEM>>>(Qb, Kb, Vb, Wq, Wk, Wv, bQ, bK, bV, Qp, Kp, Vp, QSCALE);

    // launch 3
    flash_mma<<<dim3(NSEQ / 128, NH), 256, FLASH_SMEM>>>(Qp, Kp, Vp, ctxb);

    // launch 4
    dim3 gg(DM / 128, NSEQ / 128);      // (4, 32)
    outproj_gemm<<<gg, 256, GEMM_SMEM>>>(ctxb, Wo, bO, Q, tmp);

    // launch 5
    ln_kernel<<<NSEQ, 128>>>(tmp, gamma, beta, out);
}